// round 2
// baseline (speedup 1.0000x reference)
#include <cuda_runtime.h>
#include <cuda_bf16.h>
#include <cstdint>

// ============================ problem constants ============================
#define NROWS 65536
#define DDIM  512
#define KCL   1024
#define NT    4            // N-tiles per row block (256 cols each)

// ============================ device scratch ===============================
__device__ __nv_bfloat16 g_xbf[(size_t)NROWS * DDIM];  // x in bf16 (64 MB)
__device__ __nv_bfloat16 g_cbf[KCL * DDIM];            // clusters in bf16 (1 MB)
__device__ float g_csq[KCL];                           // ||c||^2
__device__ float g_xsq[NROWS];                         // ||x||^2
__device__ float g_part[NT * NROWS];                   // per-ntile row sums

// ============================ helpers ======================================
__device__ __forceinline__ uint32_t smem_to_u32(const void* p) {
    uint32_t a;
    asm("{ .reg .u64 t; cvta.to.shared.u64 t, %1; cvt.u32.u64 %0, t; }"
        : "=r"(a) : "l"(p));
    return a;
}

__device__ __forceinline__ uint32_t pack_bf2(float a, float b) {
    __nv_bfloat162 h = __floats2bfloat162_rn(a, b);
    return *reinterpret_cast<uint32_t*>(&h);
}

// swizzled smem byte offset for (row, 16B-chunk) in a [rows x 64B] tile.
// chunk' = chunk ^ ((row>>1)&3) -> the 8 chunks touched by one ldmatrix
// (8 consecutive rows, fixed chunk) land in 8 distinct 16B bank groups.
__device__ __forceinline__ uint32_t swz(uint32_t row, uint32_t chunk) {
    return (row << 6) + (((chunk) ^ ((row >> 1) & 3u)) << 4);
}

#define CP_ASYNC_16(saddr, gaddr) \
    asm volatile("cp.async.cg.shared.global [%0], [%1], 16;" \
                 :: "r"(saddr), "l"(gaddr))
#define CP_COMMIT() asm volatile("cp.async.commit_group;" ::: "memory")
#define CP_WAIT_2() asm volatile("cp.async.wait_group 2;" ::: "memory")
#define CP_WAIT_0() asm volatile("cp.async.wait_group 0;" ::: "memory")

#define LDSM_X4(r0, r1, r2, r3, addr) \
    asm volatile("ldmatrix.sync.aligned.m8n8.x4.shared.b16 {%0,%1,%2,%3}, [%4];" \
                 : "=r"(r0), "=r"(r1), "=r"(r2), "=r"(r3) : "r"(addr))
#define LDSM_X2(r0, r1, addr) \
    asm volatile("ldmatrix.sync.aligned.m8n8.x2.shared.b16 {%0,%1}, [%2];" \
                 : "=r"(r0), "=r"(r1) : "r"(addr))

#define MMA_BF16(d0, d1, d2, d3, a0, a1, a2, a3, b0, b1) \
    asm volatile("mma.sync.aligned.m16n8k16.row.col.f32.bf16.bf16.f32 " \
                 "{%0,%1,%2,%3}, {%4,%5,%6,%7}, {%8,%9}, {%0,%1,%2,%3};" \
                 : "+f"(d0), "+f"(d1), "+f"(d2), "+f"(d3) \
                 : "r"(a0), "r"(a1), "r"(a2), "r"(a3), "r"(b0), "r"(b1))

// ============================ prep kernels =================================
// clusters: fp32 -> bf16 + ||c||^2
__global__ void prep_clusters(const float* __restrict__ cl) {
    int k = blockIdx.x;
    int t = threadIdx.x;  // 128 threads, one float4 each
    float4 v = reinterpret_cast<const float4*>(cl + (size_t)k * DDIM)[t];
    uint2 p = { pack_bf2(v.x, v.y), pack_bf2(v.z, v.w) };
    reinterpret_cast<uint2*>(g_cbf + (size_t)k * DDIM)[t] = p;
    float s = v.x * v.x + v.y * v.y + v.z * v.z + v.w * v.w;
    for (int o = 16; o; o >>= 1) s += __shfl_down_sync(0xFFFFFFFFu, s, o);
    __shared__ float ps[4];
    if ((t & 31) == 0) ps[t >> 5] = s;
    __syncthreads();
    if (t == 0) g_csq[k] = ps[0] + ps[1] + ps[2] + ps[3];
}

// x: fp32 -> bf16 + ||x||^2 (single pass over the 128 MB input)
__global__ void prep_x(const float* __restrict__ x) {
    int r = blockIdx.x;
    int t = threadIdx.x;  // 128 threads, one float4 each
    float4 v = reinterpret_cast<const float4*>(x + (size_t)r * DDIM)[t];
    uint2 p = { pack_bf2(v.x, v.y), pack_bf2(v.z, v.w) };
    reinterpret_cast<uint2*>(g_xbf + (size_t)r * DDIM)[t] = p;
    float s = v.x * v.x + v.y * v.y + v.z * v.z + v.w * v.w;
    for (int o = 16; o; o >>= 1) s += __shfl_down_sync(0xFFFFFFFFu, s, o);
    __shared__ float ps[4];
    if ((t & 31) == 0) ps[t >> 5] = s;
    __syncthreads();
    if (t == 0) g_xsq[r] = ps[0] + ps[1] + ps[2] + ps[3];
}

// ============================ main GEMM kernel =============================
// CTA tile: M=128 x N=256, K=512 in 16 chunks of 32.
// 8 warps in 2(M) x 4(N) grid; warp tile 64x64.
// 4-stage cp.async pipeline. Stage: A 128x32 bf16 (8KB) + B 256x32 bf16 (16KB).
static constexpr int STAGE_BYTES = 24576;
static constexpr int B_OFF       = 8192;
static constexpr int NSTAGE      = 4;
static constexpr int EXTRA_OFF   = NSTAGE * STAGE_BYTES;       // 98304
static constexpr int CSQ_OFF     = EXTRA_OFF;                  // 256 f
static constexpr int XSQ_OFF     = CSQ_OFF + 1024;             // 128 f
static constexpr int PART_OFF    = XSQ_OFF + 512;              // 128*4 f
static constexpr int SMEM_TOTAL  = PART_OFF + 2048;            // 101888

__global__ void __launch_bounds__(256, 1)
cluster_main_kernel(float* __restrict__ out) {
    extern __shared__ char smem[];
    const uint32_t sb = smem_to_u32(smem);
    const int t  = threadIdx.x;
    const int rt = blockIdx.x >> 2;          // row tile (adjacent CTAs share it)
    const int nt = blockIdx.x & 3;           // n tile
    const int rowbase = rt * 128;
    const int ntbase  = nt * 256;

    const int w  = t >> 5;                    // warp id
    const int l  = t & 31;                    // lane
    const int wm = w >> 2;                    // 0..1 (M)
    const int wn = w & 3;                     // 0..3 (N)
    const int group = l >> 2;                 // 0..7
    const int tid4  = l & 3;                  // 0..3

    const __nv_bfloat16* xb = g_xbf + (size_t)rowbase * DDIM;
    const __nv_bfloat16* cb = g_cbf + (size_t)ntbase * DDIM;

    // ---- stage csq/xsq slices into dedicated smem ----
    float* csq_s = reinterpret_cast<float*>(smem + CSQ_OFF);
    float* xsq_s = reinterpret_cast<float*>(smem + XSQ_OFF);
    float* ps    = reinterpret_cast<float*>(smem + PART_OFF);  // [128][4]
    if (t < 256) csq_s[t] = g_csq[ntbase + t];
    if (t < 128) xsq_s[t] = g_xsq[rowbase + t];

    // ---- per-lane cp.async slot assignments ----
    // A: 512 chunks (128 rows x 4), 2 per thread. B: 1024 chunks, 4 per thread.
    const int arow0 = t >> 2, ach = t & 3;      // + i*64 rows

    // ---- precomputed ldmatrix lane addresses (stage-relative) ----
    // A x4: mat = l>>3: row +((mat&1)<<3)+(l&7), chunk-bit = mat>>1
    uint32_t aAddr[4][2];
    {
        int r8   = (l & 7) + (((l >> 3) & 1) << 3);
        int cbit = l >> 4;
        #pragma unroll
        for (int mi = 0; mi < 4; ++mi) {
            int row = wm * 64 + mi * 16 + r8;
            aAddr[mi][0] = swz(row, cbit);
            aAddr[mi][1] = swz(row, 2 + cbit);
        }
    }
    // B x2: lanes 0-15 supply addrs: row = nj*8 + (l&7), chunk-bit = (l>>3)&1
    uint32_t bAddr[8][2];
    {
        int r8   = l & 7;
        int cbit = (l >> 3) & 1;
        #pragma unroll
        for (int nj = 0; nj < 8; ++nj) {
            int row = wn * 64 + nj * 8 + r8;
            bAddr[nj][0] = B_OFF + swz(row, cbit);
            bAddr[nj][1] = B_OFF + swz(row, 2 + cbit);
        }
    }

    // ---- stage loader ----
    auto load_stage = [&](int kc, int stg) {
        uint32_t s = sb + stg * STAGE_BYTES;
        #pragma unroll
        for (int i = 0; i < 2; ++i) {
            int row = arow0 + i * 64;
            const __nv_bfloat16* g = xb + (size_t)row * DDIM + kc * 32 + ach * 8;
            CP_ASYNC_16(s + swz(row, ach), (uint64_t)__cvta_generic_to_global(g));
        }
        #pragma unroll
        for (int i = 0; i < 4; ++i) {
            int row = arow0 + i * 64;
            const __nv_bfloat16* g = cb + (size_t)row * DDIM + kc * 32 + ach * 8;
            CP_ASYNC_16(s + B_OFF + swz(row, ach), (uint64_t)__cvta_generic_to_global(g));
        }
    };

    // ---- prefetch 3 stages ----
    #pragma unroll
    for (int p = 0; p < 3; ++p) { load_stage(p, p); CP_COMMIT(); }

    // ---- accumulators ----
    float acc[4][8][4];
    #pragma unroll
    for (int mi = 0; mi < 4; ++mi)
        #pragma unroll
        for (int nj = 0; nj < 8; ++nj)
            #pragma unroll
            for (int c = 0; c < 4; ++c) acc[mi][nj][c] = 0.f;

    // ---- main loop over 16 K-chunks ----
    #pragma unroll 1
    for (int kc = 0; kc < 16; ++kc) {
        CP_WAIT_2();
        __syncthreads();
        if (kc + 3 < 16) load_stage(kc + 3, (kc + 3) & 3);
        CP_COMMIT();

        const uint32_t s = sb + (kc & 3) * STAGE_BYTES;
        #pragma unroll
        for (int ks = 0; ks < 2; ++ks) {
            uint32_t a[4][4], b[8][2];
            #pragma unroll
            for (int mi = 0; mi < 4; ++mi)
                LDSM_X4(a[mi][0], a[mi][1], a[mi][2], a[mi][3], s + aAddr[mi][ks]);
            #pragma unroll
            for (int nj = 0; nj < 8; ++nj)
                LDSM_X2(b[nj][0], b[nj][1], s + bAddr[nj][ks]);
            #pragma unroll
            for (int mi = 0; mi < 4; ++mi)
                #pragma unroll
                for (int nj = 0; nj < 8; ++nj)
                    MMA_BF16(acc[mi][nj][0], acc[mi][nj][1],
                             acc[mi][nj][2], acc[mi][nj][3],
                             a[mi][0], a[mi][1], a[mi][2], a[mi][3],
                             b[nj][0], b[nj][1]);
        }
        __syncthreads();
    }
    CP_WAIT_0();

    // ---- fused epilogue: q, row partial sums, coalesced stores ----
    #pragma unroll
    for (int mi = 0; mi < 4; ++mi) {
        const int r0 = wm * 64 + mi * 16 + group;   // local rows
        const int r1 = r0 + 8;
        const float xs0 = xsq_s[r0], xs1 = xsq_s[r1];
        float sum0 = 0.f, sum1 = 0.f;
        #pragma unroll
        for (int nj = 0; nj < 8; ++nj) {
            const int colL = wn * 64 + nj * 8 + tid4 * 2;
            const float cs0 = csq_s[colL], cs1 = csq_s[colL + 1];
            float q00 = 1.f / (1.f + fmaxf(xs0 + cs0 - 2.f * acc[mi][nj][0], 0.f));
            float q01 = 1.f / (1.f + fmaxf(xs0 + cs1 - 2.f * acc[mi][nj][1], 0.f));
            float q10 = 1.f / (1.f + fmaxf(xs1 + cs0 - 2.f * acc[mi][nj][2], 0.f));
            float q11 = 1.f / (1.f + fmaxf(xs1 + cs1 - 2.f * acc[mi][nj][3], 0.f));
            sum0 += q00 + q01;
            sum1 += q10 + q11;
            float2* p0 = reinterpret_cast<float2*>(
                out + (size_t)(rowbase + r0) * KCL + ntbase + colL);
            float2* p1 = reinterpret_cast<float2*>(
                out + (size_t)(rowbase + r1) * KCL + ntbase + colL);
            *p0 = make_float2(q00, q01);
            *p1 = make_float2(q10, q11);
        }
        // reduce across the 4 lanes of the quad (same rows)
        sum0 += __shfl_xor_sync(0xFFFFFFFFu, sum0, 1);
        sum0 += __shfl_xor_sync(0xFFFFFFFFu, sum0, 2);
        sum1 += __shfl_xor_sync(0xFFFFFFFFu, sum1, 1);
        sum1 += __shfl_xor_sync(0xFFFFFFFFu, sum1, 2);
        if (tid4 == 0) { ps[r0 * 4 + wn] = sum0; ps[r1 * 4 + wn] = sum1; }
    }
    __syncthreads();
    if (t < 128) {
        float s = ps[t * 4 + 0] + ps[t * 4 + 1] + ps[t * 4 + 2] + ps[t * 4 + 3];
        g_part[(size_t)nt * NROWS + rowbase + t] = s;
    }
}

// ============================ normalize kernel =============================
__global__ void normalize_kernel(float* __restrict__ out) {
    int r = blockIdx.x;
    int t = threadIdx.x;  // 256 threads, float4 each -> 1024 cols
    float inv = 1.f / (g_part[r] + g_part[NROWS + r] +
                       g_part[2 * (size_t)NROWS + r] + g_part[3 * (size_t)NROWS + r]);
    float4* p = reinterpret_cast<float4*>(out + (size_t)r * KCL);
    float4 v = p[t];
    v.x *= inv; v.y *= inv; v.z *= inv; v.w *= inv;
    p[t] = v;
}

// ============================ launch =======================================
extern "C" void kernel_launch(void* const* d_in, const int* in_sizes, int n_in,
                              void* d_out, int out_size) {
    const float* x  = (const float*)d_in[0];   // (65536, 512)
    const float* cl = (const float*)d_in[1];   // (1024, 512)
    float* out = (float*)d_out;                // (65536, 1024)
    (void)in_sizes; (void)n_in; (void)out_size;

    cudaFuncSetAttribute(cluster_main_kernel,
                         cudaFuncAttributeMaxDynamicSharedMemorySize, SMEM_TOTAL);

    prep_clusters<<<KCL, 128>>>(cl);
    prep_x<<<NROWS, 128>>>(x);
    cluster_main_kernel<<<(NROWS / 128) * NT, 256, SMEM_TOTAL>>>(out);
    normalize_kernel<<<NROWS, 256>>>(out);
}

// round 3
// speedup vs baseline: 1.2235x; 1.2235x over previous
#include <cuda_runtime.h>
#include <cuda_bf16.h>
#include <cstdint>

// ============================ problem constants ============================
#define NROWS 65536
#define DDIM  512
#define KCL   1024

// ============================ device scratch ===============================
__device__ __nv_bfloat16 g_xbf[(size_t)NROWS * DDIM];  // x in bf16 (64 MB)
__device__ __nv_bfloat16 g_cbf[KCL * DDIM];            // clusters in bf16 (1 MB)
__device__ float g_csq[KCL];                           // ||c||^2
__device__ float g_xsq[NROWS];                         // ||x||^2

// ============================ helpers ======================================
__device__ __forceinline__ uint32_t smem_to_u32(const void* p) {
    uint32_t a;
    asm("{ .reg .u64 t; cvta.to.shared.u64 t, %1; cvt.u32.u64 %0, t; }"
        : "=r"(a) : "l"(p));
    return a;
}

__device__ __forceinline__ uint32_t pack_bf2(float a, float b) {
    __nv_bfloat162 h = __floats2bfloat162_rn(a, b);
    return *reinterpret_cast<uint32_t*>(&h);
}

// swizzled smem byte offset for (row, 16B-chunk) in a [rows x 64B] tile.
__device__ __forceinline__ uint32_t swz(uint32_t row, uint32_t chunk) {
    return (row << 6) + (((chunk) ^ ((row >> 1) & 3u)) << 4);
}

#define CP_ASYNC_16(saddr, gaddr) \
    asm volatile("cp.async.cg.shared.global [%0], [%1], 16;" \
                 :: "r"(saddr), "l"(gaddr))
#define CP_COMMIT() asm volatile("cp.async.commit_group;" ::: "memory")
#define CP_WAIT_2() asm volatile("cp.async.wait_group 2;" ::: "memory")

#define LDSM_X4(r0, r1, r2, r3, addr) \
    asm volatile("ldmatrix.sync.aligned.m8n8.x4.shared.b16 {%0,%1,%2,%3}, [%4];" \
                 : "=r"(r0), "=r"(r1), "=r"(r2), "=r"(r3) : "r"(addr))
#define LDSM_X2(r0, r1, addr) \
    asm volatile("ldmatrix.sync.aligned.m8n8.x2.shared.b16 {%0,%1}, [%2];" \
                 : "=r"(r0), "=r"(r1) : "r"(addr))

#define MMA_BF16(d0, d1, d2, d3, a0, a1, a2, a3, b0, b1) \
    asm volatile("mma.sync.aligned.m16n8k16.row.col.f32.bf16.bf16.f32 " \
                 "{%0,%1,%2,%3}, {%4,%5,%6,%7}, {%8,%9}, {%0,%1,%2,%3};" \
                 : "+f"(d0), "+f"(d1), "+f"(d2), "+f"(d3) \
                 : "r"(a0), "r"(a1), "r"(a2), "r"(a3), "r"(b0), "r"(b1))

// ============================ prep kernels =================================
__global__ void prep_clusters(const float* __restrict__ cl) {
    int k = blockIdx.x;
    int t = threadIdx.x;  // 128 threads, one float4 each
    float4 v = reinterpret_cast<const float4*>(cl + (size_t)k * DDIM)[t];
    uint2 p = { pack_bf2(v.x, v.y), pack_bf2(v.z, v.w) };
    reinterpret_cast<uint2*>(g_cbf + (size_t)k * DDIM)[t] = p;
    float s = v.x * v.x + v.y * v.y + v.z * v.z + v.w * v.w;
    for (int o = 16; o; o >>= 1) s += __shfl_down_sync(0xFFFFFFFFu, s, o);
    __shared__ float ps[4];
    if ((t & 31) == 0) ps[t >> 5] = s;
    __syncthreads();
    if (t == 0) g_csq[k] = ps[0] + ps[1] + ps[2] + ps[3];
}

__global__ void prep_x(const float* __restrict__ x) {
    int r = blockIdx.x;
    int t = threadIdx.x;  // 128 threads, one float4 each
    float4 v = reinterpret_cast<const float4*>(x + (size_t)r * DDIM)[t];
    uint2 p = { pack_bf2(v.x, v.y), pack_bf2(v.z, v.w) };
    reinterpret_cast<uint2*>(g_xbf + (size_t)r * DDIM)[t] = p;
    float s = v.x * v.x + v.y * v.y + v.z * v.z + v.w * v.w;
    for (int o = 16; o; o >>= 1) s += __shfl_down_sync(0xFFFFFFFFu, s, o);
    __shared__ float ps[4];
    if ((t & 31) == 0) ps[t >> 5] = s;
    __syncthreads();
    if (t == 0) g_xsq[r] = ps[0] + ps[1] + ps[2] + ps[3];
}

// ============================ main kernel ==================================
// One CTA per 128-row block. A (128x512 bf16, 128KB) resident in smem.
// Loop 4 N-tiles of 256: B streamed via 4-stage cp.async ring (16KB/stage),
// fused q-epilogue with deterministic row sums, then in-CTA renormalization
// of the 512KB output slab while it is still L2-resident.
static constexpr int A_BYTES    = 128 * 512 * 2;               // 131072
static constexpr int B_OFF      = A_BYTES;
static constexpr int B_STAGE    = 16384;
static constexpr int NSTAGE     = 4;
static constexpr int CSQ_OFF    = B_OFF + NSTAGE * B_STAGE;    // 196608 (1024 f)
static constexpr int XSQ_OFF    = CSQ_OFF + 4096;              // (128 f)
static constexpr int PS_OFF     = XSQ_OFF + 512;               // (512 f)
static constexpr int RSUM_OFF   = PS_OFF + 2048;               // (128 f)
static constexpr int SMEM_TOTAL = RSUM_OFF + 512;              // 204288

__global__ void __launch_bounds__(256, 1)
cluster_main_kernel(float* __restrict__ out) {
    extern __shared__ char smem[];
    const uint32_t sb = smem_to_u32(smem);
    const int t  = threadIdx.x;
    const int rowbase = blockIdx.x * 128;

    const int w  = t >> 5;                    // warp id
    const int l  = t & 31;                    // lane
    const int wm = w >> 2;                    // 0..1 (M)
    const int wn = w & 3;                     // 0..3 (N)
    const int group = l >> 2;                 // 0..7
    const int tid4  = l & 3;                  // 0..3

    const __nv_bfloat16* xb = g_xbf + (size_t)rowbase * DDIM;

    float* csq_s  = reinterpret_cast<float*>(smem + CSQ_OFF);
    float* xsq_s  = reinterpret_cast<float*>(smem + XSQ_OFF);
    float* ps     = reinterpret_cast<float*>(smem + PS_OFF);   // [128][4]
    float* rsum_s = reinterpret_cast<float*>(smem + RSUM_OFF); // [128]

    // stage csq (all 1024), xsq (128 rows), zero rsum
    #pragma unroll
    for (int i = 0; i < 4; ++i) csq_s[t + i * 256] = g_csq[t + i * 256];
    if (t < 128) { xsq_s[t] = g_xsq[rowbase + t]; rsum_s[t] = 0.f; }

    // ---- B-stage loader for pipeline iteration idx in [0,64) ----
    const int brow0 = t >> 2, bch = t & 3;
    auto load_B = [&](int idx) {
        const int nt = idx >> 4, kc = idx & 15;
        const uint32_t s = sb + B_OFF + (idx & 3) * B_STAGE;
        const __nv_bfloat16* cbT = g_cbf + (size_t)(nt * 256) * DDIM;
        #pragma unroll
        for (int i = 0; i < 4; ++i) {
            int row = brow0 + i * 64;
            const __nv_bfloat16* g = cbT + (size_t)row * DDIM + kc * 32 + bch * 8;
            CP_ASYNC_16(s + swz(row, bch), (uint64_t)__cvta_generic_to_global(g));
        }
    };

    // ---- group 0: full A tile (16 chunks of 128x32) + B stage 0 ----
    #pragma unroll
    for (int c = 0; c < 16; ++c) {
        #pragma unroll
        for (int i = 0; i < 2; ++i) {
            int u = t + i * 256;
            int r = u >> 2, j = u & 3;
            const __nv_bfloat16* g = xb + (size_t)r * DDIM + c * 32 + j * 8;
            CP_ASYNC_16(sb + c * 8192 + swz(r, j), (uint64_t)__cvta_generic_to_global(g));
        }
    }
    load_B(0);
    CP_COMMIT();
    load_B(1); CP_COMMIT();
    load_B(2); CP_COMMIT();

    // ---- precomputed ldmatrix lane offsets (chunk/stage-relative) ----
    uint32_t aAddr[4][2];
    {
        int r8   = (l & 7) + (((l >> 3) & 1) << 3);
        int cbit = l >> 4;
        #pragma unroll
        for (int mi = 0; mi < 4; ++mi) {
            int row = wm * 64 + mi * 16 + r8;
            aAddr[mi][0] = swz(row, cbit);
            aAddr[mi][1] = swz(row, 2 + cbit);
        }
    }
    uint32_t bAddr[8][2];
    {
        int r8   = l & 7;
        int cbit = (l >> 3) & 1;
        #pragma unroll
        for (int nj = 0; nj < 8; ++nj) {
            int row = wn * 64 + nj * 8 + r8;
            bAddr[nj][0] = swz(row, cbit);
            bAddr[nj][1] = swz(row, 2 + cbit);
        }
    }

    float acc[4][8][4];
    #pragma unroll
    for (int mi = 0; mi < 4; ++mi)
        #pragma unroll
        for (int nj = 0; nj < 8; ++nj)
            #pragma unroll
            for (int c = 0; c < 4; ++c) acc[mi][nj][c] = 0.f;

    // ---- unified 64-iteration pipeline: 4 N-tiles x 16 K-chunks ----
    #pragma unroll 1
    for (int nt = 0; nt < 4; ++nt) {
        #pragma unroll 1
        for (int kc = 0; kc < 16; ++kc) {
            const int idx = nt * 16 + kc;
            CP_WAIT_2();
            __syncthreads();
            if (idx + 3 < 64) load_B(idx + 3);
            CP_COMMIT();

            const uint32_t sA = sb + kc * 8192;
            const uint32_t sBs = sb + B_OFF + (idx & 3) * B_STAGE;
            #pragma unroll
            for (int ks = 0; ks < 2; ++ks) {
                uint32_t a[4][4], b[8][2];
                #pragma unroll
                for (int mi = 0; mi < 4; ++mi)
                    LDSM_X4(a[mi][0], a[mi][1], a[mi][2], a[mi][3], sA + aAddr[mi][ks]);
                #pragma unroll
                for (int nj = 0; nj < 8; ++nj)
                    LDSM_X2(b[nj][0], b[nj][1], sBs + bAddr[nj][ks]);
                #pragma unroll
                for (int mi = 0; mi < 4; ++mi)
                    #pragma unroll
                    for (int nj = 0; nj < 8; ++nj)
                        MMA_BF16(acc[mi][nj][0], acc[mi][nj][1],
                                 acc[mi][nj][2], acc[mi][nj][3],
                                 a[mi][0], a[mi][1], a[mi][2], a[mi][3],
                                 b[nj][0], b[nj][1]);
            }
        }

        // ---- epilogue for this N-tile: q, partial row sums, store ----
        const int ntbase = nt * 256;
        #pragma unroll
        for (int mi = 0; mi < 4; ++mi) {
            const int r0 = wm * 64 + mi * 16 + group;
            const int r1 = r0 + 8;
            const float xs0 = xsq_s[r0], xs1 = xsq_s[r1];
            float sum0 = 0.f, sum1 = 0.f;
            #pragma unroll
            for (int nj = 0; nj < 8; ++nj) {
                const int colL = wn * 64 + nj * 8 + tid4 * 2;
                const float cs0 = csq_s[ntbase + colL], cs1 = csq_s[ntbase + colL + 1];
                float q00 = __fdividef(1.f, 1.f + fmaxf(xs0 + cs0 - 2.f * acc[mi][nj][0], 0.f));
                float q01 = __fdividef(1.f, 1.f + fmaxf(xs0 + cs1 - 2.f * acc[mi][nj][1], 0.f));
                float q10 = __fdividef(1.f, 1.f + fmaxf(xs1 + cs0 - 2.f * acc[mi][nj][2], 0.f));
                float q11 = __fdividef(1.f, 1.f + fmaxf(xs1 + cs1 - 2.f * acc[mi][nj][3], 0.f));
                sum0 += q00 + q01;
                sum1 += q10 + q11;
                acc[mi][nj][0] = 0.f; acc[mi][nj][1] = 0.f;
                acc[mi][nj][2] = 0.f; acc[mi][nj][3] = 0.f;
                *reinterpret_cast<float2*>(
                    out + (size_t)(rowbase + r0) * KCL + ntbase + colL) = make_float2(q00, q01);
                *reinterpret_cast<float2*>(
                    out + (size_t)(rowbase + r1) * KCL + ntbase + colL) = make_float2(q10, q11);
            }
            sum0 += __shfl_xor_sync(0xFFFFFFFFu, sum0, 1);
            sum0 += __shfl_xor_sync(0xFFFFFFFFu, sum0, 2);
            sum1 += __shfl_xor_sync(0xFFFFFFFFu, sum1, 1);
            sum1 += __shfl_xor_sync(0xFFFFFFFFu, sum1, 2);
            if (tid4 == 0) { ps[r0 * 4 + wn] = sum0; ps[r1 * 4 + wn] = sum1; }
        }
        __syncthreads();
        if (t < 128)
            rsum_s[t] += ps[t * 4 + 0] + ps[t * 4 + 1] + ps[t * 4 + 2] + ps[t * 4 + 3];
        __syncthreads();
    }

    // ---- fused renormalization (output slab still L2-resident) ----
    if (t < 128) rsum_s[t] = __fdividef(1.f, rsum_s[t]);
    __syncthreads();
    float4* op = reinterpret_cast<float4*>(out + (size_t)rowbase * KCL);
    #pragma unroll 4
    for (int r = 0; r < 128; ++r) {
        float iv = rsum_s[r];
        float4 v = op[(size_t)r * 256 + t];
        v.x *= iv; v.y *= iv; v.z *= iv; v.w *= iv;
        op[(size_t)r * 256 + t] = v;
    }
}

// ============================ launch =======================================
extern "C" void kernel_launch(void* const* d_in, const int* in_sizes, int n_in,
                              void* d_out, int out_size) {
    const float* x  = (const float*)d_in[0];   // (65536, 512)
    const float* cl = (const float*)d_in[1];   // (1024, 512)
    float* out = (float*)d_out;                // (65536, 1024)
    (void)in_sizes; (void)n_in; (void)out_size;

    cudaFuncSetAttribute(cluster_main_kernel,
                         cudaFuncAttributeMaxDynamicSharedMemorySize, SMEM_TOTAL);

    prep_clusters<<<KCL, 128>>>(cl);
    prep_x<<<NROWS, 128>>>(x);
    cluster_main_kernel<<<NROWS / 128, 256, SMEM_TOTAL>>>(out);
}